// round 14
// baseline (speedup 1.0000x reference)
#include <cuda_runtime.h>
#include <cuda_bf16.h>
#include <cstdint>
#include <cstddef>

// Problem constants
#define BATCH 4
#define C_IN  256
#define CI    128
#define NPIX  4096   // 64*64
#define GSPLIT 8     // split-K for Gram

// ---------------------------------------------------------------------------
// Scratch (allocation-free: __device__ globals)
// ---------------------------------------------------------------------------
__device__ __nv_bfloat16 g_bhi[(size_t)BATCH * C_IN * NPIX];  // b split  [B][c][m]
__device__ __nv_bfloat16 g_blo[(size_t)BATCH * C_IN * NPIX];
__device__ __nv_bfloat16 g_aThi[(size_t)BATCH * NPIX * C_IN]; // a^T split [B][n][c]
__device__ __nv_bfloat16 g_aTlo[(size_t)BATCH * NPIX * C_IN];
__device__ float g_rs[(size_t)BATCH * C_IN];                  // rowsum of b
__device__ float g_u [(size_t)BATCH * CI];                    // Wg  . rowsum
__device__ float g_v [(size_t)BATCH * CI];                    // Wphi. rowsum
__device__ float g_Gpart[(size_t)BATCH * GSPLIT * C_IN * C_IN];
__device__ float g_Gram [(size_t)BATCH * C_IN * C_IN];        // b b^T
__device__ float g_G1[(size_t)BATCH * CI * C_IN];             // Wg.Gram
__device__ float g_G2[(size_t)BATCH * CI * CI];               // M^T (w/ bias)
__device__ float g_G3[(size_t)BATCH * CI * C_IN];             // M^T.Wtheta
__device__ float g_bthf[(size_t)BATCH * CI];                  // M^T.btheta
__device__ __nv_bfloat16 g_Wfh[(size_t)BATCH * C_IN * C_IN];  // Wfin split
__device__ __nv_bfloat16 g_Wfl[(size_t)BATCH * C_IN * C_IN];
__device__ float g_bfin[(size_t)BATCH * C_IN];

// ---------------------------------------------------------------------------
// PTX helpers (baseline features only: valid under compute_103)
// ---------------------------------------------------------------------------
__device__ __forceinline__ uint32_t smem_u32(const void* p) {
    uint32_t a;
    asm("{ .reg .u64 t; cvta.to.shared.u64 t, %1; cvt.u32.u64 %0, t; }"
        : "=r"(a) : "l"(p));
    return a;
}

#define LDM_X4(r, a)                                                          \
    asm volatile("ldmatrix.sync.aligned.m8n8.x4.shared.b16 {%0,%1,%2,%3}, [%4];" \
        : "=r"((r)[0]), "=r"((r)[1]), "=r"((r)[2]), "=r"((r)[3]) : "r"(a))

__device__ __forceinline__ void mma16816(float* d, const uint32_t* a,
                                         uint32_t b0, uint32_t b1) {
    asm("mma.sync.aligned.m16n8k16.row.col.f32.bf16.bf16.f32 "
        "{%0,%1,%2,%3}, {%4,%5,%6,%7}, {%8,%9}, {%0,%1,%2,%3};"
        : "+f"(d[0]), "+f"(d[1]), "+f"(d[2]), "+f"(d[3])
        : "r"(a[0]), "r"(a[1]), "r"(a[2]), "r"(a[3]), "r"(b0), "r"(b1));
}

#define CP16(dst, src)                                                        \
    asm volatile("cp.async.cg.shared.global [%0], [%1], 16;"                  \
                 :: "r"(dst), "l"(src) : "memory")
#define CP_COMMIT() asm volatile("cp.async.commit_group;" ::: "memory")
#define CP_WAIT0()  asm volatile("cp.async.wait_group 0;" ::: "memory")

__device__ __forceinline__ uint32_t pk(float a, float b) {
    uint32_t ua = (uint32_t)__bfloat16_as_ushort(__float2bfloat16(a));
    uint32_t ub = (uint32_t)__bfloat16_as_ushort(__float2bfloat16(b));
    return ua | (ub << 16);
}
__device__ __forceinline__ void split2(float a, float b,
                                       uint32_t& hi, uint32_t& lo) {
    __nv_bfloat16 ha = __float2bfloat16(a), hb = __float2bfloat16(b);
    hi = (uint32_t)__bfloat16_as_ushort(ha) |
         ((uint32_t)__bfloat16_as_ushort(hb) << 16);
    lo = pk(a - __bfloat162float(ha), b - __bfloat162float(hb));
}

__device__ __forceinline__ void mma6(float* d0, float* d1,
                                     const uint32_t* ah, const uint32_t* al,
                                     const uint32_t* bh, const uint32_t* bl) {
    mma16816(d0, ah, bh[0], bh[1]);
    mma16816(d1, ah, bh[2], bh[3]);
    mma16816(d0, ah, bl[0], bl[1]);
    mma16816(d1, ah, bl[2], bl[3]);
    mma16816(d0, al, bh[0], bh[1]);
    mma16816(d1, al, bh[2], bh[3]);
}

// ---------------------------------------------------------------------------
// conv_split: fp32 -> bf16 hi/lo elementwise (for b; layout preserved)
// ---------------------------------------------------------------------------
__global__ __launch_bounds__(256)
void conv_split_kernel(const float* __restrict__ x,
                       uint2* __restrict__ hi, uint2* __restrict__ lo) {
    size_t i = (size_t)blockIdx.x * 256 + threadIdx.x;   // float4 index
    float4 v = ((const float4*)x)[i];
    uint32_t h0, l0, h1, l1;
    split2(v.x, v.y, h0, l0);
    split2(v.z, v.w, h1, l1);
    hi[i] = make_uint2(h0, h1);
    lo[i] = make_uint2(l0, l1);
}

// ---------------------------------------------------------------------------
// rowsum of b: rs[b][c] = sum_m b[c][m]   (one warp per row, deterministic)
// ---------------------------------------------------------------------------
__global__ __launch_bounds__(256)
void rowsum_kernel(const float* __restrict__ x, float* __restrict__ rs) {
    int row = blockIdx.x * 8 + (threadIdx.x >> 5);    // B*C_IN = 1024 rows
    int lane = threadIdx.x & 31;
    const float4* p = (const float4*)(x + (size_t)row * NPIX);
    float s = 0.f;
    for (int i = lane; i < NPIX / 4; i += 32) {
        float4 v = p[i];
        s += (v.x + v.y) + (v.z + v.w);
    }
#pragma unroll
    for (int o = 16; o; o >>= 1) s += __shfl_xor_sync(0xFFFFFFFFu, s, o);
    if (lane == 0) rs[row] = s;
}

// u = Wg.rs, v = Wphi.rs   (grid = B, 256 thr)
__global__ __launch_bounds__(256)
void uv_kernel(const float* __restrict__ wphi, const float* __restrict__ wg,
               const float* __restrict__ rs,
               float* __restrict__ u, float* __restrict__ v) {
    int bb = blockIdx.x, t = threadIdx.x;
    const float* r = rs + bb * C_IN;
    if (t < CI) {
        float s = 0.f;
        for (int c = 0; c < C_IN; c++) s += wphi[t * C_IN + c] * r[c];
        v[bb * CI + t] = s;
    } else {
        int k = t - CI;
        float s = 0.f;
        for (int c = 0; c < C_IN; c++) s += wg[k * C_IN + c] * r[c];
        u[bb * CI + k] = s;
    }
}

// ---------------------------------------------------------------------------
// convT_a: a [B][c][n] fp32 -> aT [B][n][c] bf16 hi/lo (smem transpose)
// grid (64 n-tiles, 4 c-tiles, B)
// ---------------------------------------------------------------------------
__global__ __launch_bounds__(256)
void convTa_kernel(const float* __restrict__ a,
                   __nv_bfloat16* __restrict__ hi,
                   __nv_bfloat16* __restrict__ lo) {
    __shared__ float s[64][65];
    const int nt = blockIdx.x, ct = blockIdx.y, bb = blockIdx.z;
    const int t = threadIdx.x;
#pragma unroll
    for (int i = 0; i < 4; i++) {
        int idx = t + i * 256;            // 1024 float4: r<64, c4<16
        int r = idx >> 4, c4 = idx & 15;
        float4 v = *(const float4*)&a[((size_t)bb * C_IN + ct * 64 + r) * NPIX +
                                      nt * 64 + c4 * 4];
        s[r][c4 * 4 + 0] = v.x; s[r][c4 * 4 + 1] = v.y;
        s[r][c4 * 4 + 2] = v.z; s[r][c4 * 4 + 3] = v.w;
    }
    __syncthreads();
#pragma unroll
    for (int i = 0; i < 4; i++) {
        int oid = t + i * 256;            // n<64, cq<16
        int n = oid >> 4, cq = oid & 15;
        float v0 = s[cq * 4 + 0][n], v1 = s[cq * 4 + 1][n];
        float v2 = s[cq * 4 + 2][n], v3 = s[cq * 4 + 3][n];
        uint32_t h0, l0, h1, l1;
        split2(v0, v1, h0, l0);
        split2(v2, v3, h1, l1);
        size_t o = ((size_t)bb * NPIX + nt * 64 + n) * C_IN + ct * 64 + cq * 4;
        *(uint2*)(hi + o) = make_uint2(h0, h1);
        *(uint2*)(lo + o) = make_uint2(l0, l1);
    }
}

// ---------------------------------------------------------------------------
// gram (HMMA): Gpart[b][s][r][c] = sum_{m in slice} b[r][m]*b[c][m]
// grid (4 tiles rt*2+ct, GSPLIT, B); 256 thr; slice = 512 m, chunks of 64.
// ---------------------------------------------------------------------------
#define MP_BUF  73728u
#define MP_SMEM 147456u

__device__ __forceinline__ void gram_load(uint32_t sb, int buf,
                                          const __nv_bfloat16* bhi,
                                          const __nv_bfloat16* blo,
                                          int bb, int rt, int ct, int m0,
                                          int tid) {
    uint32_t bo = sb + (uint32_t)buf * MP_BUF;
#pragma unroll
    for (int i = 0; i < 4; i++) {
        int idx = tid + i * 256;
        int ci = idx >> 3, m8 = idx & 7;
        size_t soA = ((size_t)(bb * C_IN + rt * 128 + ci)) * NPIX + m0 + m8 * 8;
        size_t soB = ((size_t)(bb * C_IN + ct * 128 + ci)) * NPIX + m0 + m8 * 8;
        uint32_t d = bo + (uint32_t)ci * 144u + (uint32_t)m8 * 16u;
        CP16(d,          bhi + soA);
        CP16(d + 18432u, blo + soA);
        CP16(d + 36864u, bhi + soB);
        CP16(d + 55296u, blo + soB);
    }
}

__global__ __launch_bounds__(256, 1)
void gram_kernel(const __nv_bfloat16* __restrict__ bhi,
                 const __nv_bfloat16* __restrict__ blo,
                 float* __restrict__ Gpart) {
    extern __shared__ char msm[];
    const uint32_t sb = smem_u32(msm);
    const int tid = threadIdx.x, lane = tid & 31, wq = tid >> 5;
    const int tile = blockIdx.x, ss = blockIdx.y, bb = blockIdx.z;
    const int rt = tile >> 1, ct = tile & 1;
    const int m0base = ss * (NPIX / GSPLIT);

    const int lm = lane & 7, mid = lane >> 3;
    const int arow = (mid & 1) * 8 + lm, acol = (mid >> 1) * 16;
    const int brow = (mid >> 1) * 8 + lm, bcol = (mid & 1) * 16;
    const int gq = lane >> 2, tig = lane & 3;

    gram_load(sb, 0, bhi, blo, bb, rt, ct, m0base, tid);
    CP_COMMIT(); CP_WAIT0();
    __syncthreads();

    float acc[16][4];
#pragma unroll
    for (int t = 0; t < 16; t++)
#pragma unroll
        for (int q = 0; q < 4; q++) acc[t][q] = 0.f;

    for (int c = 0; c < 8; c++) {
        const int buf = c & 1;
        if (c + 1 < 8) {
            gram_load(sb, buf ^ 1, bhi, blo, bb, rt, ct,
                      m0base + (c + 1) * 64, tid);
            CP_COMMIT();
        }
        const uint32_t aB = sb + (uint32_t)buf * MP_BUF +
            (uint32_t)(wq * 16 + arow) * 144u + (uint32_t)acol;
        const uint32_t bB = sb + (uint32_t)buf * MP_BUF + 36864u +
            (uint32_t)brow * 144u + (uint32_t)bcol;
#pragma unroll
        for (int kk = 0; kk < 4; kk++) {
            uint32_t ah[4], al[4];
            LDM_X4(ah, aB + 32u * kk);
            LDM_X4(al, aB + 18432u + 32u * kk);
#pragma unroll
            for (int cp = 0; cp < 8; cp++) {
                uint32_t bh[4], bl[4];
                uint32_t ga = bB + (uint32_t)(16 * cp) * 144u + 32u * kk;
                LDM_X4(bh, ga);
                LDM_X4(bl, ga + 18432u);
                mma6(acc[2 * cp], acc[2 * cp + 1], ah, al, bh, bl);
            }
        }
        if (c + 1 < 8) CP_WAIT0();
        __syncthreads();
    }

    float* dst = Gpart +
        (((size_t)(bb * GSPLIT + ss)) * C_IN + rt * 128 + wq * 16 + gq) * C_IN +
        ct * 128;
#pragma unroll
    for (int j = 0; j < 8; j++) {
        int cc = j * 16 + 2 * tig;
        *(float2*)(dst + cc)              = make_float2(acc[2*j][0],   acc[2*j][1]);
        *(float2*)(dst + cc + 8)          = make_float2(acc[2*j+1][0], acc[2*j+1][1]);
        *(float2*)(dst + 8*C_IN + cc)     = make_float2(acc[2*j][2],   acc[2*j][3]);
        *(float2*)(dst + 8*C_IN + cc + 8) = make_float2(acc[2*j+1][2], acc[2*j+1][3]);
    }
}

__global__ __launch_bounds__(256)
void gram_red_kernel(const float* __restrict__ Gpart, float* __restrict__ Gram) {
    size_t gid = (size_t)blockIdx.x * 256 + threadIdx.x;   // B*65536
    int bb = (int)(gid >> 16);
    size_t rem = gid & 65535u;
    const float* p = Gpart + (size_t)bb * GSPLIT * 65536 + rem;
    float s = 0.f;
#pragma unroll
    for (int ss = 0; ss < GSPLIT; ss++) s += p[(size_t)ss * 65536];
    Gram[gid] = s;
}

// ---------------------------------------------------------------------------
// S1: G1[b][k2][c2] = sum_c Wg[k2][c] * Gram[b][c][c2]   (K=256)
// grid (4 c2-tiles, 2 k2-tiles, B), 256 thr
// ---------------------------------------------------------------------------
#define P256 257
#define S256_SMEM (2 * 64 * P256 * 4)

__global__ __launch_bounds__(256)
void s1_kernel(const float* __restrict__ wg, const float* __restrict__ Gram,
               float* __restrict__ G1) {
    extern __shared__ float sm1[];
    float* sA = sm1;                 // [64][257] Wg rows
    float* sB = sm1 + 64 * P256;     // [64][257] sB[col][k] = Gram[k][col]
    const int bx = blockIdx.x, by = blockIdx.y, bb = blockIdx.z;
    const int t = threadIdx.x, tx = t & 15, ty = t >> 4;

#pragma unroll
    for (int i = 0; i < 16; i++) {
        int idx = t + i * 256;                  // r<64, c4<64
        int r = idx >> 6, c4 = idx & 63;
        float4 v = *(const float4*)&wg[(by * 64 + r) * C_IN + c4 * 4];
        float* d = sA + r * P256 + c4 * 4;
        d[0] = v.x; d[1] = v.y; d[2] = v.z; d[3] = v.w;
    }
#pragma unroll
    for (int i = 0; i < 16; i++) {
        int idx = t + i * 256;                  // k<256, c4<16
        int k = idx >> 4, c4 = idx & 15;
        float4 v = *(const float4*)&Gram[(size_t)bb * 65536 + k * C_IN +
                                         bx * 64 + c4 * 4];
        sB[(c4 * 4 + 0) * P256 + k] = v.x;
        sB[(c4 * 4 + 1) * P256 + k] = v.y;
        sB[(c4 * 4 + 2) * P256 + k] = v.z;
        sB[(c4 * 4 + 3) * P256 + k] = v.w;
    }
    __syncthreads();

    float acc[4][4];
#pragma unroll
    for (int i = 0; i < 4; i++)
#pragma unroll
        for (int j = 0; j < 4; j++) acc[i][j] = 0.f;
#pragma unroll 4
    for (int k = 0; k < 256; k++) {
        float af[4], bf[4];
#pragma unroll
        for (int i = 0; i < 4; i++) af[i] = sA[(4 * ty + i) * P256 + k];
#pragma unroll
        for (int j = 0; j < 4; j++) bf[j] = sB[(4 * tx + j) * P256 + k];
#pragma unroll
        for (int i = 0; i < 4; i++)
#pragma unroll
            for (int j = 0; j < 4; j++) acc[i][j] += af[i] * bf[j];
    }
#pragma unroll
    for (int i = 0; i < 4; i++)
#pragma unroll
        for (int j = 0; j < 4; j++)
            G1[((size_t)bb * CI + by * 64 + 4 * ty + i) * C_IN +
               bx * 64 + 4 * tx + j] = acc[i][j];
}

// ---------------------------------------------------------------------------
// S2: G2[b][c'][k] = sum_c2 G1[b][c'][c2]*Wphi[k][c2]
//                  + u[b][c']*bphi[k] + bg[c']*(v[b][k] + N*bphi[k])
// grid (2 k-tiles, 2 c'-tiles, B)
// ---------------------------------------------------------------------------
__global__ __launch_bounds__(256)
void s2_kernel(const float* __restrict__ G1, const float* __restrict__ wphi,
               const float* __restrict__ u, const float* __restrict__ v,
               const float* __restrict__ bphi, const float* __restrict__ bg,
               float* __restrict__ G2) {
    extern __shared__ float sm2[];
    float* sA = sm2;                 // [64][257] G1 rows (c')
    float* sB = sm2 + 64 * P256;     // [64][257] Wphi rows (k)
    const int bx = blockIdx.x, by = blockIdx.y, bb = blockIdx.z;
    const int t = threadIdx.x, tx = t & 15, ty = t >> 4;

#pragma unroll
    for (int i = 0; i < 16; i++) {
        int idx = t + i * 256;
        int r = idx >> 6, c4 = idx & 63;
        float4 v4 = *(const float4*)&G1[((size_t)bb * CI + by * 64 + r) * C_IN +
                                        c4 * 4];
        float* d = sA + r * P256 + c4 * 4;
        d[0] = v4.x; d[1] = v4.y; d[2] = v4.z; d[3] = v4.w;
    }
#pragma unroll
    for (int i = 0; i < 16; i++) {
        int idx = t + i * 256;
        int r = idx >> 6, c4 = idx & 63;
        float4 v4 = *(const float4*)&wphi[(bx * 64 + r) * C_IN + c4 * 4];
        float* d = sB + r * P256 + c4 * 4;
        d[0] = v4.x; d[1] = v4.y; d[2] = v4.z; d[3] = v4.w;
    }
    __syncthreads();

    float acc[4][4];
#pragma unroll
    for (int i = 0; i < 4; i++)
#pragma unroll
        for (int j = 0; j < 4; j++) acc[i][j] = 0.f;
#pragma unroll 4
    for (int k = 0; k < 256; k++) {
        float af[4], bf[4];
#pragma unroll
        for (int i = 0; i < 4; i++) af[i] = sA[(4 * ty + i) * P256 + k];
#pragma unroll
        for (int j = 0; j < 4; j++) bf[j] = sB[(4 * tx + j) * P256 + k];
#pragma unroll
        for (int i = 0; i < 4; i++)
#pragma unroll
            for (int j = 0; j < 4; j++) acc[i][j] += af[i] * bf[j];
    }
#pragma unroll
    for (int i = 0; i < 4; i++) {
        int row = by * 64 + 4 * ty + i;
        float ur = u[bb * CI + row], bgr = bg[row];
#pragma unroll
        for (int j = 0; j < 4; j++) {
            int col = bx * 64 + 4 * tx + j;
            float val = acc[i][j] + ur * bphi[col] +
                        bgr * (v[bb * CI + col] + (float)NPIX * bphi[col]);
            G2[((size_t)bb * CI + row) * CI + col] = val;
        }
    }
}

// ---------------------------------------------------------------------------
// S3: G3[b][c'][c] = sum_k G2[b][c'][k]*Wtheta[k][c]  (K=128)
//     bthf[b][c'] = sum_k G2[b][c'][k]*btheta[k]   (on bx==0)
// grid (4 c-tiles, 2 c'-tiles, B)
// ---------------------------------------------------------------------------
#define P128 129
#define S128_SMEM ((2 * 64 * P128 + 128) * 4)

__global__ __launch_bounds__(256)
void s3_kernel(const float* __restrict__ G2, const float* __restrict__ wtheta,
               const float* __restrict__ btheta,
               float* __restrict__ G3, float* __restrict__ bthf) {
    extern __shared__ float sm3[];
    float* sA = sm3;                  // [64][129] G2 rows (c')
    float* sB = sm3 + 64 * P128;      // [64][129] sB[col][k] = Wtheta[k][col]
    float* sbt = sm3 + 2 * 64 * P128; // [128] btheta
    const int bx = blockIdx.x, by = blockIdx.y, bb = blockIdx.z;
    const int t = threadIdx.x, tx = t & 15, ty = t >> 4;

#pragma unroll
    for (int i = 0; i < 8; i++) {
        int idx = t + i * 256;                  // r<64, c4<32
        int r = idx >> 5, c4 = idx & 31;
        float4 v4 = *(const float4*)&G2[((size_t)bb * CI + by * 64 + r) * CI +
                                        c4 * 4];
        float* d = sA + r * P128 + c4 * 4;
        d[0] = v4.x; d[1] = v4.y; d[2] = v4.z; d[3] = v4.w;
    }
#pragma unroll
    for (int i = 0; i < 8; i++) {
        int idx = t + i * 256;                  // k<128, c4<16
        int k = idx >> 4, c4 = idx & 15;
        float4 v4 = *(const float4*)&wtheta[k * C_IN + bx * 64 + c4 * 4];
        sB[(c4 * 4 + 0) * P128 + k] = v4.x;
        sB[(c4 * 4 + 1) * P128 + k] = v4.y;
        sB[(c4 * 4 + 2) * P128 + k] = v4.z;
        sB[(c4 * 4 + 3) * P128 + k] = v4.w;
    }
    if (t < 128) sbt[t] = btheta[t];
    __syncthreads();

    float acc[4][4];
#pragma unroll
    for (int i = 0; i < 4; i++)
#pragma unroll
        for (int j = 0; j < 4; j++) acc[i][j] = 0.f;
#pragma unroll 4
    for (int k = 0; k < 128; k++) {
        float af[4], bf[4];
#pragma unroll
        for (int i = 0; i < 4; i++) af[i] = sA[(4 * ty + i) * P128 + k];
#pragma unroll
        for (int j = 0; j < 4; j++) bf[j] = sB[(4 * tx + j) * P128 + k];
#pragma unroll
        for (int i = 0; i < 4; i++)
#pragma unroll
            for (int j = 0; j < 4; j++) acc[i][j] += af[i] * bf[j];
    }
#pragma unroll
    for (int i = 0; i < 4; i++)
#pragma unroll
        for (int j = 0; j < 4; j++)
            G3[((size_t)bb * CI + by * 64 + 4 * ty + i) * C_IN +
               bx * 64 + 4 * tx + j] = acc[i][j];

    if (bx == 0 && t < 64) {
        float s = 0.f;
        for (int k = 0; k < 128; k++) s += sA[t * P128 + k] * sbt[k];
        bthf[bb * CI + by * 64 + t] = s;
    }
}

// ---------------------------------------------------------------------------
// S4: Wfin[b][co][c] = s[co] * sum_c' Ww[co][c']*G3[b][c'][c]  (K=128)
//     s[co] = gamma*rsqrt(var+eps)/N ; split to bf16 hi/lo.
//     bfin[b][co] = s[co]*sum Ww*bthf + beta - mean*gamma*rsqrt (bx==0)
// grid (4 c-tiles, 4 co-tiles, B)
// ---------------------------------------------------------------------------
__global__ __launch_bounds__(256)
void s4_kernel(const float* __restrict__ Ww, const float* __restrict__ G3,
               const float* __restrict__ bthf,
               const float* __restrict__ gamma, const float* __restrict__ var,
               const float* __restrict__ beta, const float* __restrict__ mean,
               __nv_bfloat16* __restrict__ Wfh, __nv_bfloat16* __restrict__ Wfl,
               float* __restrict__ bfin) {
    extern __shared__ float sm4[];
    float* sA = sm4;                  // [64][129] Ww rows (co)
    float* sB = sm4 + 64 * P128;      // [64][129] sB[col][c'] = G3[c'][col]
    float* sbf = sm4 + 2 * 64 * P128; // [128] bthf
    const int bx = blockIdx.x, by = blockIdx.y, bb = blockIdx.z;
    const int t = threadIdx.x, tx = t & 15, ty = t >> 4;

#pragma unroll
    for (int i = 0; i < 8; i++) {
        int idx = t + i * 256;
        int r = idx >> 5, c4 = idx & 31;
        float4 v4 = *(const float4*)&Ww[(by * 64 + r) * CI + c4 * 4];
        float* d = sA + r * P128 + c4 * 4;
        d[0] = v4.x; d[1] = v4.y; d[2] = v4.z; d[3] = v4.w;
    }
#pragma unroll
    for (int i = 0; i < 8; i++) {
        int idx = t + i * 256;                  // cp<128, c4<16
        int cp = idx >> 4, c4 = idx & 15;
        float4 v4 = *(const float4*)&G3[((size_t)bb * CI + cp) * C_IN +
                                        bx * 64 + c4 * 4];
        sB[(c4 * 4 + 0) * P128 + cp] = v4.x;
        sB[(c4 * 4 + 1) * P128 + cp] = v4.y;
        sB[(c4 * 4 + 2) * P128 + cp] = v4.z;
        sB[(c4 * 4 + 3) * P128 + cp] = v4.w;
    }
    if (t < 128) sbf[t] = bthf[bb * CI + t];
    __syncthreads();

    float acc[4][4];
#pragma unroll
    for (int i = 0; i < 4; i++)
#pragma unroll
        for (int j = 0; j < 4; j++) acc[i][j] = 0.f;
#pragma unroll 4
    for (int k = 0; k < 128; k++) {
        float af[4], bf[4];
#pragma unroll
        for (int i = 0; i < 4; i++) af[i] = sA[(4 * ty + i) * P128 + k];
#pragma unroll
        for (int j = 0; j < 4; j++) bf[j] = sB[(4 * tx + j) * P128 + k];
#pragma unroll
        for (int i = 0; i < 4; i++)
#pragma unroll
            for (int j = 0; j < 4; j++) acc[i][j] += af[i] * bf[j];
    }
#pragma unroll
    for (int i = 0; i < 4; i++) {
        int co = by * 64 + 4 * ty + i;
        float Abn = gamma[co] * rsqrtf(var[co] + 1e-5f);
        float sc = Abn * (1.0f / (float)NPIX);
        size_t o = ((size_t)bb * C_IN + co) * C_IN + bx * 64 + 4 * tx;
        uint32_t h, l;
        split2(acc[i][0] * sc, acc[i][1] * sc, h, l);
        *(uint32_t*)(Wfh + o) = h; *(uint32_t*)(Wfl + o) = l;
        split2(acc[i][2] * sc, acc[i][3] * sc, h, l);
        *(uint32_t*)(Wfh + o + 2) = h; *(uint32_t*)(Wfl + o + 2) = l;
    }
    if (bx == 0 && t < 64) {
        int co = by * 64 + t;
        float s = 0.f;
        for (int k = 0; k < 128; k++) s += sA[t * P128 + k] * sbf[k];
        float Abn = gamma[co] * rsqrtf(var[co] + 1e-5f);
        bfin[bb * C_IN + co] = s * Abn * (1.0f / (float)NPIX) +
                               beta[co] - mean[co] * Abn;
    }
}

// ---------------------------------------------------------------------------
// out (HMMA): out[b][co][n] = sum_c Wfin[b][co][c]*aT[b][n][c] + bfin[b][co]
// CTA [256 co][128 n], K=256 in two chunks of 128. 512 thr / 16 warps.
// grid (32 n-tiles, B)
// ---------------------------------------------------------------------------
#define OU_PITCH 272u
#define OU_AH 0u
#define OU_AL 69632u
#define OU_BH 139264u
#define OU_BL 174080u
#define OU_SMEM 208896u

__global__ __launch_bounds__(512, 1)
void out_mma_kernel(const __nv_bfloat16* __restrict__ Wfh,
                    const __nv_bfloat16* __restrict__ Wfl,
                    const __nv_bfloat16* __restrict__ aThi,
                    const __nv_bfloat16* __restrict__ aTlo,
                    const float* __restrict__ bfin,
                    float* __restrict__ out) {
    extern __shared__ char osm[];
    const uint32_t sb = smem_u32(osm);
    const int tid = threadIdx.x, lane = tid & 31, wid = tid >> 5;
    const int n0 = blockIdx.x * 128, bb = blockIdx.y;

    const int lm = lane & 7, mid = lane >> 3;
    const int arow = (mid & 1) * 8 + lm, acolB = (mid >> 1) * 16;
    const int brow = (mid >> 1) * 8 + lm, bcolB = (mid & 1) * 16;

    float yacc[16][4];
#pragma unroll
    for (int t = 0; t < 16; t++)
#pragma unroll
        for (int j = 0; j < 4; j++) yacc[t][j] = 0.f;

    for (int kc = 0; kc < 2; kc++) {
        // stage A = Wfin chunk [256 co][128 c] hi/lo
#pragma unroll
        for (int i = 0; i < 8; i++) {
            int idx = tid + i * 512;
            int r = idx >> 4, g = idx & 15;
            size_t so = ((size_t)bb * C_IN + r) * C_IN + kc * 128 + g * 8;
            uint32_t d = sb + OU_AH + (uint32_t)r * OU_PITCH + 16u * (uint32_t)g;
            CP16(d, Wfh + so);
            CP16(d + (OU_AL - OU_AH), Wfl + so);
        }
        // stage B = aT chunk [128 n][128 c] hi/lo
#pragma unroll
        for (int i = 0; i < 4; i++) {
            int idx = tid + i * 512;
            int r = idx >> 4, g = idx & 15;
            size_t so = ((size_t)bb * NPIX + n0 + r) * C_IN + kc * 128 + g * 8;
            uint32_t d = sb + OU_BH + (uint32_t)r * OU_PITCH + 16u * (uint32_t)g;
            CP16(d, aThi + so);
            CP16(d + (OU_BL - OU_BH), aTlo + so);
        }
        CP_COMMIT();
        CP_WAIT0();
        __syncthreads();

        const uint32_t aB = sb + OU_AH +
            (uint32_t)(wid * 16 + arow) * OU_PITCH + (uint32_t)acolB;
#pragma unroll
        for (int kk = 0; kk < 8; kk++) {
            uint32_t ah[4], al[4];
            LDM_X4(ah, aB + 32u * kk);
            LDM_X4(al, aB + (OU_AL - OU_AH) + 32u * kk);
#pragma unroll
            for (int np = 0; np < 8; np++) {
                uint32_t bh[4], bl[4];
                uint32_t bAddr = sb + OU_BH +
                    (uint32_t)(np * 16 + brow) * OU_PITCH + (uint32_t)bcolB +
                    32u * kk;
                LDM_X4(bh, bAddr);
                LDM_X4(bl, bAddr + (OU_BL - OU_BH));
                mma6(yacc[2 * np], yacc[2 * np + 1], ah, al, bh, bl);
            }
        }
        __syncthreads();
    }

    const int gq = lane >> 2, tig = lane & 3;
    const int cA = wid * 16 + gq;
    const int cB = cA + 8;
    const float b0 = bfin[bb * C_IN + cA];
    const float b1 = bfin[bb * C_IN + cB];
#pragma unroll
    for (int t = 0; t < 16; t++) {
        int n = n0 + (t >> 1) * 16 + (t & 1) * 8 + 2 * tig;
        size_t o0 = ((size_t)bb * C_IN + cA) * NPIX + n;
        size_t o1 = ((size_t)bb * C_IN + cB) * NPIX + n;
        *(float2*)(out + o0) = make_float2(yacc[t][0] + b0, yacc[t][1] + b0);
        *(float2*)(out + o1) = make_float2(yacc[t][2] + b1, yacc[t][3] + b1);
    }
}

// ---------------------------------------------------------------------------
// Launch
// ---------------------------------------------------------------------------
extern "C" void kernel_launch(void* const* d_in, const int* in_sizes, int n_in,
                              void* d_out, int out_size) {
    const float* a       = (const float*)d_in[0];
    const float* b       = (const float*)d_in[1];
    const float* theta_w = (const float*)d_in[2];
    const float* theta_b = (const float*)d_in[3];
    const float* phi_w   = (const float*)d_in[4];
    const float* phi_b   = (const float*)d_in[5];
    const float* g_w     = (const float*)d_in[6];
    const float* g_b     = (const float*)d_in[7];
    const float* W_w     = (const float*)d_in[8];
    const float* bn_g    = (const float*)d_in[9];
    const float* bn_be   = (const float*)d_in[10];
    const float* bn_m    = (const float*)d_in[11];
    const float* bn_v    = (const float*)d_in[12];
    float* out = (float*)d_out;

    __nv_bfloat16 *bhi, *blo, *aThi, *aTlo, *Wfh, *Wfl;
    float *rs, *u, *v, *Gpart, *Gram, *G1, *G2, *G3, *bthf, *bfin;
    cudaGetSymbolAddress((void**)&bhi, g_bhi);
    cudaGetSymbolAddress((void**)&blo, g_blo);
    cudaGetSymbolAddress((void**)&aThi, g_aThi);
    cudaGetSymbolAddress((void**)&aTlo, g_aTlo);
    cudaGetSymbolAddress((void**)&rs, g_rs);
    cudaGetSymbolAddress((void**)&u, g_u);
    cudaGetSymbolAddress((void**)&v, g_v);
    cudaGetSymbolAddress((void**)&Gpart, g_Gpart);
    cudaGetSymbolAddress((void**)&Gram, g_Gram);
    cudaGetSymbolAddress((void**)&G1, g_G1);
    cudaGetSymbolAddress((void**)&G2, g_G2);
    cudaGetSymbolAddress((void**)&G3, g_G3);
    cudaGetSymbolAddress((void**)&bthf, g_bthf);
    cudaGetSymbolAddress((void**)&Wfh, g_Wfh);
    cudaGetSymbolAddress((void**)&Wfl, g_Wfl);
    cudaGetSymbolAddress((void**)&bfin, g_bfin);

    cudaFuncSetAttribute(gram_kernel,
                         cudaFuncAttributeMaxDynamicSharedMemorySize, MP_SMEM);
    cudaFuncSetAttribute(s1_kernel,
                         cudaFuncAttributeMaxDynamicSharedMemorySize, S256_SMEM);
    cudaFuncSetAttribute(s2_kernel,
                         cudaFuncAttributeMaxDynamicSharedMemorySize, S256_SMEM);
    cudaFuncSetAttribute(s3_kernel,
                         cudaFuncAttributeMaxDynamicSharedMemorySize, S128_SMEM);
    cudaFuncSetAttribute(s4_kernel,
                         cudaFuncAttributeMaxDynamicSharedMemorySize, S128_SMEM);
    cudaFuncSetAttribute(out_mma_kernel,
                         cudaFuncAttributeMaxDynamicSharedMemorySize, OU_SMEM);

    // independent front-end
    conv_split_kernel<<<BATCH * C_IN * NPIX / 4 / 256, 256>>>(
        b, (uint2*)bhi, (uint2*)blo);
    rowsum_kernel<<<BATCH * C_IN / 8, 256>>>(b, rs);
    uv_kernel<<<BATCH, 256>>>(phi_w, g_w, rs, u, v);
    convTa_kernel<<<dim3(NPIX / 64, C_IN / 64, BATCH), 256>>>(a, aThi, aTlo);

    // Gram = b.b^T
    gram_kernel<<<dim3(4, GSPLIT, BATCH), 256, MP_SMEM>>>(bhi, blo, Gpart);
    gram_red_kernel<<<BATCH * C_IN * C_IN / 256, 256>>>(Gpart, Gram);

    // small chain: Wfin = (A/N).Ww.Wg.Gram.Wphi^T.Wtheta (+ bias folds)
    s1_kernel<<<dim3(4, 2, BATCH), 256, S256_SMEM>>>(g_w, Gram, G1);
    s2_kernel<<<dim3(2, 2, BATCH), 256, S256_SMEM>>>(G1, phi_w, u, v,
                                                     phi_b, g_b, G2);
    s3_kernel<<<dim3(4, 2, BATCH), 256, S128_SMEM>>>(G2, theta_w, theta_b,
                                                     G3, bthf);
    s4_kernel<<<dim3(4, 4, BATCH), 256, S128_SMEM>>>(W_w, G3, bthf,
                                                     bn_g, bn_v, bn_be, bn_m,
                                                     Wfh, Wfl, bfin);

    // out = Wfin.a + bfin
    out_mma_kernel<<<dim3(NPIX / 128, BATCH), 512, OU_SMEM>>>(
        Wfh, Wfl, aThi, aTlo, bfin, out);
}